// round 1
// baseline (speedup 1.0000x reference)
#include <cuda_runtime.h>
#include <math_constants.h>

// Dilate (5x5 per-channel max filter, SAME padding) over (64, 384, 384, 3) fp32.
// Output shape (B,H,W,C,1) == same linear layout / element count as input.
//
// Layout trick: collapse W and C into a fused dimension L = W*C = 1152 floats.
// Horizontal window taps (pixels +-1,+-2 along W) become fused-dim offsets
// +-3, +-6 — always within the same channel. Loads/stores stay fully coalesced.
//
// Fused separable max: load tile (+halo) to SMEM, vertical 5-max into a second
// SMEM buffer, horizontal 5-max out of that, single HBM read + single write.

#define B_   64
#define H_   384
#define W_   384
#define C_   3
#define L_   (W_ * C_)         // 1152
#define TX   128               // fused-dim cols per block
#define TY   16                // rows per block
#define RAD  2                 // k=5 radius (pixels)
#define HALO (RAD * C_)        // 6 fused cols each side
#define SH_W (TX + 2 * HALO)   // 140
#define SH_H (TY + 2 * RAD)    // 20

__global__ __launch_bounds__(TX)
void dilate5_kernel(const float* __restrict__ in,
                    const int* __restrict__ kptr,
                    float* __restrict__ out)
{
    const int k = *kptr;
    const int tid = threadIdx.x;
    const int b   = blockIdx.z;
    const int row0 = blockIdx.y * TY;   // first output row of this block
    const int col0 = blockIdx.x * TX;   // first output fused-col of this block

    if (k == 5) {
        // ---------------- fast tiled path (k = 5) ----------------
        __shared__ float tile[SH_H][SH_W];
        __shared__ float vbuf[TY][SH_W];

        const int grow0 = row0 - RAD;
        const int gcol0 = col0 - HALO;

        // cooperative load with -inf padding at image edges
        #pragma unroll 4
        for (int i = tid; i < SH_H * SH_W; i += TX) {
            const int ry = i / SH_W;
            const int rx = i - ry * SH_W;
            const int gy = grow0 + ry;
            const int gx = gcol0 + rx;
            float v = -CUDART_INF_F;
            if (gy >= 0 && gy < H_ && gx >= 0 && gx < L_)
                v = in[((size_t)b * H_ + gy) * L_ + gx];
            tile[ry][rx] = v;
        }
        __syncthreads();

        // vertical 5-max for every loaded column
        #pragma unroll 4
        for (int i = tid; i < TY * SH_W; i += TX) {
            const int ry = i / SH_W;
            const int rx = i - ry * SH_W;
            float m = tile[ry][rx];
            m = fmaxf(m, tile[ry + 1][rx]);
            m = fmaxf(m, tile[ry + 2][rx]);
            m = fmaxf(m, tile[ry + 3][rx]);
            m = fmaxf(m, tile[ry + 4][rx]);
            vbuf[ry][rx] = m;
        }
        __syncthreads();

        // horizontal 5-max (taps at fused offsets 0,3,6,9,12) + store
        const int tx = tid;
        #pragma unroll
        for (int ty = 0; ty < TY; ty++) {
            float m = vbuf[ty][tx];
            m = fmaxf(m, vbuf[ty][tx + 3]);
            m = fmaxf(m, vbuf[ty][tx + 6]);
            m = fmaxf(m, vbuf[ty][tx + 9]);
            m = fmaxf(m, vbuf[ty][tx + 12]);
            out[((size_t)b * H_ + (row0 + ty)) * L_ + (col0 + tx)] = m;
        }
    } else {
        // ---------------- generic fallback (any k), SAME padding ----------------
        const int padL = (k - 1) / 2;
        const int tx = tid;
        const int ox = col0 + tx;          // fused col
        const int w  = ox / C_;
        const int c  = ox - w * C_;
        for (int ty = 0; ty < TY; ty++) {
            const int oy = row0 + ty;
            float m = -CUDART_INF_F;
            for (int ky = 0; ky < k; ky++) {
                const int gy = oy - padL + ky;
                if (gy < 0 || gy >= H_) continue;
                for (int kx = 0; kx < k; kx++) {
                    const int gw = w - padL + kx;
                    if (gw < 0 || gw >= W_) continue;
                    m = fmaxf(m, in[((size_t)b * H_ + gy) * L_ + gw * C_ + c]);
                }
            }
            out[((size_t)b * H_ + oy) * L_ + ox] = m;
        }
    }
}

extern "C" void kernel_launch(void* const* d_in, const int* in_sizes, int n_in,
                              void* d_out, int out_size)
{
    const float* images = (const float*)d_in[0];
    const int*   kptr   = (const int*)d_in[1];
    float*       out    = (float*)d_out;

    dim3 grid(L_ / TX, H_ / TY, B_);   // 9 x 24 x 64
    dim3 block(TX);
    dilate5_kernel<<<grid, block>>>(images, kptr, out);
}

// round 2
// speedup vs baseline: 1.6564x; 1.6564x over previous
#include <cuda_runtime.h>
#include <math_constants.h>

// 5x5 per-channel max filter (cv2.dilate), SAME padding, (64,384,384,3) fp32.
// Fused dim L = W*C = 1152 floats = 288 float4. One block spans a full fused
// row (no x-halo), 288 threads, TY output rows per block.
//
// Vertical 5-max: per-thread float4 ring over TY+4 streamed rows -> SMEM.
// Horizontal 5-max (taps 0,+-3,+-6 in fused cols): 5 aligned LDS.128 -> 4 outputs.

#define B_    64
#define H_    384
#define L_    1152
#define L4_   288            // float4 per fused row
#define TY    8              // output rows per block
#define NT    288            // threads = L4_
#define GUARD 8              // -inf guard words each side (keeps LDS.128 aligned)
#define SW    (GUARD + L_ + GUARD)   // 1168 words per smem row

__device__ __forceinline__ float4 f4max(float4 a, float4 b) {
    return make_float4(fmaxf(a.x, b.x), fmaxf(a.y, b.y),
                       fmaxf(a.z, b.z), fmaxf(a.w, b.w));
}

__global__ __launch_bounds__(NT, 4)
void dilate5_kernel(const float* __restrict__ in,
                    const int* __restrict__ kptr,
                    float* __restrict__ out)
{
    const int k   = *kptr;
    const int tid = threadIdx.x;
    const int b   = blockIdx.y;
    const int y0  = blockIdx.x * TY;      // first output row

    if (k == 5) {
        __shared__ float sm[TY][SW];

        // -inf guards (8 words each side of every smem row)
        if (tid < TY * 2 * GUARD) {                 // 128 threads
            const int ty = tid / (2 * GUARD);
            const int j  = tid % (2 * GUARD);
            const int ix = (j < GUARD) ? j : (GUARD + L_) + (j - GUARD);
            sm[ty][ix] = -CUDART_INF_F;
        }

        const float4* inb  = (const float4*)in  + (size_t)b * H_ * L4_;
        float4*       outb = (float4*)      out + (size_t)b * H_ * L4_;

        // ---- vertical pass: stream TY+4 rows, 5-row ring in registers ----
        float4 ring[5];
        #pragma unroll
        for (int r = 0; r < TY + 4; ++r) {
            const int y = y0 - 2 + r;
            float4 v;
            if (y >= 0 && y < H_)
                v = __ldg(&inb[(size_t)y * L4_ + tid]);
            else
                v = make_float4(-CUDART_INF_F, -CUDART_INF_F,
                                -CUDART_INF_F, -CUDART_INF_F);
            ring[r % 5] = v;
            if (r >= 4) {
                float4 m = f4max(f4max(f4max(ring[0], ring[1]),
                                       f4max(ring[2], ring[3])), ring[4]);
                *(float4*)(&sm[r - 4][GUARD + 4 * tid]) = m;
            }
        }
        __syncthreads();

        // ---- horizontal pass: 5 aligned LDS.128 -> 4 outputs ----
        // v[i] = vmax[4*tid + i - 8]; out col x = 4*tid+j needs taps
        // vmax[x-6, x-3, x, x+3, x+6] -> v indices {j+2, j+5, j+8, j+11, j+14}.
        #pragma unroll
        for (int ty = 0; ty < TY; ++ty) {
            const float4* rp = (const float4*)(&sm[ty][4 * tid]);
            const float4 a0 = rp[0];
            const float4 a1 = rp[1];
            const float4 a2 = rp[2];
            const float4 a3 = rp[3];
            const float4 a4 = rp[4];

            float4 o;
            // j=0: v2,v5,v8,v11,v14  = a0.z a1.y a2.x a2.w a3.z
            o.x = fmaxf(fmaxf(fmaxf(a0.z, a1.y), fmaxf(a2.x, a2.w)), a3.z);
            // j=1: v3,v6,v9,v12,v15  = a0.w a1.z a2.y a3.x a3.w
            o.y = fmaxf(fmaxf(fmaxf(a0.w, a1.z), fmaxf(a2.y, a3.x)), a3.w);
            // j=2: v4,v7,v10,v13,v16 = a1.x a1.w a2.z a3.y a4.x
            o.z = fmaxf(fmaxf(fmaxf(a1.x, a1.w), fmaxf(a2.z, a3.y)), a4.x);
            // j=3: v5,v8,v11,v14,v17 = a1.y a2.x a2.w a3.z a4.y
            o.w = fmaxf(fmaxf(fmaxf(a1.y, a2.x), fmaxf(a2.w, a3.z)), a4.y);

            outb[(size_t)(y0 + ty) * L4_ + tid] = o;
        }
    } else {
        // ---------------- generic fallback (any odd k), SAME padding ----------------
        const int padL = (k - 1) / 2;
        const int C = 3, W = 384;
        #pragma unroll
        for (int j = 0; j < 4; ++j) {
            const int x = 4 * tid + j;        // fused col
            const int w = x / C;
            const int c = x - w * C;
            for (int ty = 0; ty < TY; ++ty) {
                const int oy = y0 + ty;
                float m = -CUDART_INF_F;
                for (int ky = 0; ky < k; ky++) {
                    const int gy = oy - padL + ky;
                    if (gy < 0 || gy >= H_) continue;
                    for (int kx = 0; kx < k; kx++) {
                        const int gw = w - padL + kx;
                        if (gw < 0 || gw >= W) continue;
                        m = fmaxf(m, in[((size_t)b * H_ + gy) * L_ + gw * C + c]);
                    }
                }
                out[((size_t)b * H_ + oy) * L_ + x] = m;
            }
        }
    }
}

extern "C" void kernel_launch(void* const* d_in, const int* in_sizes, int n_in,
                              void* d_out, int out_size)
{
    const float* images = (const float*)d_in[0];
    const int*   kptr   = (const int*)d_in[1];
    float*       out    = (float*)d_out;

    dim3 grid(H_ / TY, B_);    // 48 x 64
    dim3 block(NT);            // 288
    dilate5_kernel<<<grid, block>>>(images, kptr, out);
}